// round 16
// baseline (speedup 1.0000x reference)
#include <cuda_runtime.h>
#include <math.h>

#define SMEM_ROWS 1024     // head-row cap; freeze expected at ~290 rows
#define NTHREADS  256
#define NBLOCKS   592      // 4 blocks/SM * 148 SMs -> single co-resident wave

// ---------------------------------------------------------------------------
// R16: analytic fast path. One thread per block solves the SIR final-size
// relation (8 Newton steps on log2f) -> (S_inf, R_inf, cut) in ~300 cycles,
// broadcast via smem. Fill blocks (1..591) then start the 13-us constant fill
// IMMEDIATELY (no serial prologue on their critical path). Block 0 runs the
// exact R12 serial scan and writes head rows + geometric transition rows
// (chunked running-product: 1 exp2f per 16 rows -- avoids the R10 MUFU
// concentration trap); its ~3.5 us hides under the fill. Analytic constants
// deviate from the scan-frozen state by ~1e-5 relative (discretization +
// fp32 rounding), far inside the 1e-3 gate. A deterministic `ok` guard
// (subcritical, 1e-4 < u < 0.99, predicted freeze < 850, Newton converged)
// reverts ALL blocks to the proven R12 path otherwise.
//
// Recurrence (single rounding per value):
//   u = 1-g+beff*S ; nI = I*u ; nS = fma(-beff*I,S,S) ; nR = fma(g,I,R)
// S monotone non-increasing => bitwise-stable over a 32-iter chunk with
// 0<u<1 means frozen forever; tail exactly geometric then constant.
// `cut` = round4(182/(-log2 u) + 64) exceeds the freeze row by construction
// (freeze needs only ~26+log2(beff*I0) <= 33 decay bits), so the fill region
// [cut, steps) and block 0's region [0, cut) never overlap.
// ---------------------------------------------------------------------------
__global__ void __launch_bounds__(NTHREADS)
sir_fused_kernel(const float* __restrict__ x,
                 const float* __restrict__ bw,
                 const float* __restrict__ gw,
                 int steps, int total_elems,
                 float* __restrict__ out)
{
    __shared__ __align__(16) float2 s_SI[SMEM_ROWS];   // 8 KB (block 0 / fallback)
    __shared__ int    s_ok, s_cutA;
    __shared__ float  s_Sa, s_RinfA;
    __shared__ int    s_nrows, s_r, s_cut, s_frozen;
    __shared__ float  s_S, s_Irec, s_A, s_Rinf, s_pop, s_x2, s_u;
    __shared__ double s_c;

    const int tid = threadIdx.x;

    // ---------- Phase 0: analytic solve (thread 0 of EVERY block) ----------
    if (tid == 0) {
        const float x0 = x[0], x1 = x[1], x2 = x[2];
        const float pop  = __fadd_rn(__fadd_rn(x0, x1), x2);
        const float g    = gw[0];
        const float beff = (pop == 1.0f) ? bw[0] : __fdiv_rn(bw[0], pop);
        s_pop = pop; s_x2 = x2;

        int ok = (steps > 2048) && (x0 > 0.0f) && (x1 >= 0.0f) && (pop > 0.0f)
              && (g > 1e-6f) && (g < 1.0f) && (beff >= 0.0f) && (beff < 100.0f);

        float Sa = x0, RinfA = 0.0f;
        long long cutA = 0;
        if (ok) {
            // psi(S) = log2(S) - log2(S0) + K2*(pop - S - R0);  K2 = beff/(g*ln2)
            const float K2   = __fmul_rn(__fdiv_rn(beff, g), 1.44269504f);
            const float l2S0 = log2f(x0);
            if (1.44269504f / x0 - K2 < 0.05f) ok = 0;   // need psi' > 0 (subcritical)
            if (ok) {
                #pragma unroll
                for (int it = 0; it < 8; ++it) {
                    float psi = log2f(Sa) - l2S0 + K2 * (pop - Sa - x2);
                    float dps = 1.44269504f / Sa - K2;
                    Sa = Sa - psi / dps;
                    Sa = fminf(fmaxf(Sa, 1e-6f), x0);
                }
                float psi = log2f(Sa) - l2S0 + K2 * (pop - Sa - x2);
                if (!(fabsf(psi) < 1e-4f)) ok = 0;
                RinfA = pop - Sa;
                const float ua = 1.0f - g + beff * Sa;
                if (!(ua > 1e-4f && ua < 0.99f)) ok = 0;
                if (ok) {
                    const double ca = log2((double)ua);               // < 0
                    const double bi = (double)beff * (double)fmaxf(x1, 1e-30f);
                    const double npred = (log2(bi) + 26.0) / (-ca);   // S-freeze row
                    if (!(npred < 850.0)) ok = 0;                     // scan cap margin
                    const double n160 = 182.0 / (-ca) + 64.0;         // > npred always
                    cutA = ((long long)n160 + 3) / 4 * 4;             // multiple of 4
                }
            }
        }
        s_ok = ok; s_Sa = Sa; s_RinfA = RinfA; s_cutA = (int)cutA;
    }
    __syncthreads();

    const int okA = s_ok;

    // ================= FILL BLOCKS (analytic fast path) ====================
    if (okA && blockIdx.x != 0) {
        const float S    = s_Sa;
        const float Rinf = s_RinfA;
        const int   cut  = s_cutA;          // may exceed steps -> empty loop
        const int   n4   = total_elems / 4;
        const int   start4 = (cut >= steps) ? n4 : (3 * cut) / 4;  // cut%4==0
        const int   fgid  = (blockIdx.x - 1) * NTHREADS + tid;
        const int   fsize = (NBLOCKS - 1) * NTHREADS;   // 151296, % 3 == 0

        int j = start4 + fgid;
        const int ph = j % 3;               // constant per thread
        const float4 P = (ph == 0) ? make_float4(S,    0.0f, Rinf, S)
                       : (ph == 1) ? make_float4(0.0f, Rinf, S,    0.0f)
                                   : make_float4(Rinf, S,    0.0f, Rinf);
        float4* out4 = reinterpret_cast<float4*>(out);
        for (; j < n4; j += fsize)
            out4[j] = P;
        return;
    }

    // ============ R12 serial prologue (block 0; or ALL blocks if !ok) ======
    if (tid == 0) {
        const float x0 = x[0], x1 = x[1], x2 = x[2];
        float S = x0, I = x1, R = x2;
        const float pop  = s_pop;
        const float g    = gw[0];
        const float beff = (pop == 1.0f) ? bw[0] : __fdiv_rn(bw[0], pop);
        const float omg  = __fsub_rn(1.0f, g);

        s_SI[0] = make_float2(S, I);

        int i = 1;
        for (int h = 0; h < 3 && i < steps; ++h, ++i) {     // head rows 1..3
            float u  = __fmaf_rn(beff, S, omg);
            float v  = __fmul_rn(beff, I);
            float nI = __fmul_rn(I, u);
            float nS = __fmaf_rn(-v, S, S);
            float nR = __fmaf_rn(g, I, R);
            S = nS; I = nI; R = nR;
            s_SI[i] = make_float2(S, I);
        }

        bool frozen = false;
        const int cap = (steps < SMEM_ROWS) ? steps : SMEM_ROWS;
        for (; i + 32 <= cap; i += 32) {                    // 1 branch / 32 iters
            const float S0 = S;
            float2* w = s_SI + i;
            #pragma unroll
            for (int k = 0; k < 32; ++k) {
                float u  = __fmaf_rn(beff, S, omg);
                float v  = __fmul_rn(beff, I);
                float nI = __fmul_rn(I, u);
                float nS = __fmaf_rn(-v, S, S);
                float nR = __fmaf_rn(g, I, R);
                S = nS; I = nI; R = nR;
                w[k] = make_float2(S, I);                   // single STS.64
            }
            if (S == S0) {
                float u = __fmaf_rn(beff, S, omg);
                if (u < 1.0f && u > 0.0f) { i += 32; frozen = true; break; }
            }
        }

        if (frozen) {
            const int r_row = i - 1;
            const float  u  = __fmaf_rn(beff, S, omg);
            const double ud = (double)u;
            const double c  = log2(ud);                    // < 0
            const double Ad = (double)g * (double)I / (1.0 - ud);
            const double Rinf = (double)R + Ad;

            double mx = fmax((double)I, Ad);
            if (mx < 1e-300) mx = 1e-300;
            double t_d = (160.0 + log2(mx)) / (-c);
            long long cut_ll = r_row + (long long)t_d + 8;
            long long cut4   = ((cut_ll + 3) / 4) * 4;
            if (cut4 < (long long)i) cut4 = i;
            int cut = (cut4 > (long long)steps) ? steps : (int)cut4;

            s_nrows = i; s_r = r_row; s_cut = cut; s_frozen = 1;
            s_S = S; s_Irec = I; s_A = (float)Ad; s_Rinf = (float)Rinf;
            s_c = c; s_u = u;
        } else {
            // Fallback: finish serially to gmem (exact R from the chain).
            s_nrows = i; s_r = steps - 1; s_cut = steps; s_frozen = 0;
            for (; i < steps; ++i) {
                float u  = __fmaf_rn(beff, S, omg);
                float v  = __fmul_rn(beff, I);
                float nI = __fmul_rn(I, u);
                float nS = __fmaf_rn(-v, S, S);
                float nR = __fmaf_rn(g, I, R);
                S = nS; I = nI; R = nR;
                out[3*i] = S; out[3*i+1] = I; out[3*i+2] = R;
            }
            s_S = S; s_Irec = I; s_A = 0.0f; s_Rinf = R; s_c = 0.0; s_u = 0.0f;
        }
    }

    __syncthreads();

    const int   nrows  = s_nrows;
    const int   r      = s_r;
    const int   frozen = s_frozen;
    const float S      = s_S;
    const float Irec   = s_Irec;
    const float A      = s_A;
    const float Rinf   = s_Rinf;
    const float pop    = s_pop;
    const float uf     = s_u;
    const double c     = s_c;

    if (okA) {
        // ============ BLOCK 0, analytic mode: [0, cutA) only ===============
        const int tEnd = (s_cutA < steps) ? s_cutA : steps;

        // (a) Head rows [0, nrows): gather from s_SI; R = pop - S - I.
        {
            const int nelem = 3 * nrows;
            for (int e = tid; e < nelem; e += NTHREADS) {
                const int k    = e / 3;
                const int comp = e - 3 * k;
                const float2 si = s_SI[k];
                float val;
                if (comp == 0)      val = si.x;
                else if (comp == 1) val = si.y;
                else                val = (k == 0) ? s_x2
                                         : __fsub_rn(__fsub_rn(pop, si.x), si.y);
                out[e] = val;
            }
        }

        if (frozen) {
            // (b) Transition rows [nrows, tEnd): chunked running product —
            // 1 exp2f per 16 rows, then p *= u.
            const int CH = 16;
            for (int base = nrows + tid * CH; base < tEnd; base += NTHREADS * CH) {
                float p = exp2f((float)((double)(base - r) * c));
                const int lim = (base + CH < tEnd) ? base + CH : tEnd;
                for (int k = base; k < lim; ++k) {
                    out[3*k + 0] = S;
                    out[3*k + 1] = __fmul_rn(Irec, p);
                    out[3*k + 2] = __fmaf_rn(-A, p, Rinf);
                    p = __fmul_rn(p, uf);
                }
            }

            // (c) Scalar remainder (total_elems % 4 != 0; fill wrote float4s only).
            if (tid == 0) {
                const int e0 = (total_elems / 4) * 4;
                for (int e = e0; e < total_elems; ++e) {
                    const int k    = e / 3;
                    const int comp = e - 3 * k;
                    if (k >= tEnd)
                        out[e] = (comp == 0) ? s_Sa : ((comp == 1) ? 0.0f : s_RinfA);
                    else if (k >= nrows) {
                        const float p = exp2f((float)((double)(k - r) * c));
                        out[e] = (comp == 0) ? S
                               : (comp == 1) ? __fmul_rn(Irec, p)
                                             : __fmaf_rn(-A, p, Rinf);
                    } else {
                        const float2 si = s_SI[k];
                        out[e] = (comp == 0) ? si.x
                               : (comp == 1) ? si.y
                                             : __fsub_rn(__fsub_rn(pop, si.x), si.y);
                    }
                }
            }
        }
        return;
    }

    // ================= FALLBACK (!ok): exact R12 epilogue ==================
    {
        const int gsize = gridDim.x * NTHREADS;
        const int gtid  = blockIdx.x * NTHREADS + tid;
        const int cut   = s_cut;

        // (a) Head rows.
        {
            const int nelem = 3 * nrows;
            for (int e = gtid; e < nelem; e += gsize) {
                const int k    = e / 3;
                const int comp = e - 3 * k;
                const float2 si = s_SI[k];
                float val;
                if (comp == 0)      val = si.x;
                else if (comp == 1) val = si.y;
                else                val = (k == 0) ? s_x2
                                         : __fsub_rn(__fsub_rn(pop, si.x), si.y);
                out[e] = val;
            }
        }
        // (b) Transition rows.
        {
            const int eBeg = 3 * nrows;
            const int eEnd = 3 * cut;
            for (int e = eBeg + gtid; e < eEnd; e += gsize) {
                const int k    = e / 3;
                const int comp = e - 3 * k;
                const float p  = exp2f((float)((double)(k - r) * c));
                out[e] = (comp == 0) ? S
                       : (comp == 1) ? __fmul_rn(Irec, p)
                                     : __fmaf_rn(-A, p, Rinf);
            }
        }
        // (c) Constant fill.
        {
            const int n4     = total_elems / 4;
            const int start4 = (3 * cut) / 4;
            const float4 P0 = make_float4(S,    0.0f, Rinf, S);
            const float4 P1 = make_float4(0.0f, Rinf, S,    0.0f);
            const float4 P2 = make_float4(Rinf, S,    0.0f, Rinf);
            float4* out4 = reinterpret_cast<float4*>(out);
            int j  = start4 + gtid;
            int ph = j % 3;
            for (; j < n4; j += gsize) {
                out4[j] = (ph == 0) ? P0 : ((ph == 1) ? P1 : P2);
                ph += 1; if (ph >= 3) ph -= 3;      // gsize % 3 == 1
            }
            if (gtid == 0) {
                for (int e = n4 * 4; e < total_elems; ++e) {
                    const int k    = e / 3;
                    const int comp = e - 3 * k;
                    if (k >= cut)
                        out[e] = (comp == 0) ? S : ((comp == 1) ? 0.0f : Rinf);
                    else if (k >= nrows) {
                        const float p = exp2f((float)((double)(k - r) * c));
                        out[e] = (comp == 0) ? S
                               : (comp == 1) ? __fmul_rn(Irec, p)
                                             : __fmaf_rn(-A, p, Rinf);
                    } else {
                        const float2 si = s_SI[k];
                        out[e] = (comp == 0) ? si.x
                               : (comp == 1) ? si.y
                                             : __fsub_rn(__fsub_rn(pop, si.x), si.y);
                    }
                }
            }
        }
    }
}

extern "C" void kernel_launch(void* const* d_in, const int* in_sizes, int n_in,
                              void* d_out, int out_size)
{
    const float* x  = (const float*)d_in[0];
    const float* bw = (const float*)d_in[1];
    const float* gw = (const float*)d_in[2];
    float* out = (float*)d_out;

    const int steps = out_size / 3;

    sir_fused_kernel<<<NBLOCKS, NTHREADS>>>(x, bw, gw, steps, out_size, out);
}

// round 17
// speedup vs baseline: 1.5038x; 1.5038x over previous
#include <cuda_runtime.h>
#include <math.h>

#define SMEM_ROWS 1024     // head-row cap; freeze expected at ~290 rows
#define NTHREADS  256
#define NBLOCKS   592      // 4 blocks/SM * 148 SMs -> single co-resident wave

// ---------------------------------------------------------------------------
// Final kernel (R12 structure — empirical best, 16.9/17.1 us reproduced):
//  * Every block's thread 0 runs the serial SIR recurrence into its own SMEM,
//    storing (S, I) per row as one STS.64 (R stays in the register chain;
//    head-row R reconstructed as pop - S - I, drift ~1e-6 abs, row 0 exact).
//  * After S bitwise-freezes (monotone => permanent once a 32-iter chunk
//    leaves it unchanged with 0<u<1), the tail is exactly geometric:
//    I_m = Irec*u^m, R_m = Rinf - A*u^m; past `cut` rows are (S, 0, Rinf).
//  * All threads of all blocks then grid-stride evenly over: head rows (smem),
//    transition rows (exp2f closed form), and the constant fill — simple
//    1-float4-per-iteration stream at the L2-write-bandwidth ceiling
//    (~3.6 TB/s). Measured invariants: the ceiling holds across scalar/vec/
//    tiled/TMA shapes; ANY deviation from this exact fill loop (wider
//    per-thread footprint R13, constant-phase 591-block variants R11/R16)
//    regresses. Do not touch the fill loop.
//
// Recurrence (single rounding per value):
//   u = 1-g+beff*S ; nI = I*u ; nS = fma(-beff*I,S,S) ; nR = fma(g,I,R)
// ---------------------------------------------------------------------------
__global__ void __launch_bounds__(NTHREADS)
sir_fused_kernel(const float* __restrict__ x,
                 const float* __restrict__ bw,
                 const float* __restrict__ gw,
                 int steps, int total_elems,
                 float* __restrict__ out)
{
    __shared__ __align__(16) float2 s_SI[SMEM_ROWS];   // 8 KB: (S, I) per row
    __shared__ int    s_nrows, s_r, s_cut;
    __shared__ float  s_S, s_Irec, s_A, s_Rinf, s_pop, s_x2;
    __shared__ double s_c;

    const int tid = threadIdx.x;

    // ---------------- Prologue: serial scan (thread 0 of every block) ------
    if (tid == 0) {
        const float x0 = x[0], x1 = x[1], x2 = x[2];
        float S = x0, I = x1, R = x2;
        const float pop  = __fadd_rn(__fadd_rn(x0, x1), x2);
        const float g    = gw[0];
        const float beff = (pop == 1.0f) ? bw[0] : __fdiv_rn(bw[0], pop);
        const float omg  = __fsub_rn(1.0f, g);

        s_pop = pop; s_x2 = x2;
        s_SI[0] = make_float2(S, I);

        int i = 1;
        for (int h = 0; h < 3 && i < steps; ++h, ++i) {     // head rows 1..3
            float u  = __fmaf_rn(beff, S, omg);
            float v  = __fmul_rn(beff, I);
            float nI = __fmul_rn(I, u);
            float nS = __fmaf_rn(-v, S, S);
            float nR = __fmaf_rn(g, I, R);
            S = nS; I = nI; R = nR;
            s_SI[i] = make_float2(S, I);
        }

        bool frozen = false;
        const int cap = (steps < SMEM_ROWS) ? steps : SMEM_ROWS;
        for (; i + 32 <= cap; i += 32) {                    // 1 branch / 32 iters
            const float S0 = S;
            float2* w = s_SI + i;
            #pragma unroll
            for (int k = 0; k < 32; ++k) {
                float u  = __fmaf_rn(beff, S, omg);
                float v  = __fmul_rn(beff, I);
                float nI = __fmul_rn(I, u);
                float nS = __fmaf_rn(-v, S, S);
                float nR = __fmaf_rn(g, I, R);
                S = nS; I = nI; R = nR;
                w[k] = make_float2(S, I);                   // single STS.64
            }
            if (S == S0) {
                float u = __fmaf_rn(beff, S, omg);
                if (u < 1.0f && u > 0.0f) { i += 32; frozen = true; break; }
            }
        }

        if (frozen) {
            const int r_row = i - 1;
            const float  u  = __fmaf_rn(beff, S, omg);
            const double ud = (double)u;
            const double c  = log2(ud);                    // < 0
            const double Ad = (double)g * (double)I / (1.0 - ud);
            const double Rinf = (double)R + Ad;

            double mx = fmax((double)I, Ad);
            if (mx < 1e-300) mx = 1e-300;
            double t_d = (160.0 + log2(mx)) / (-c);        // u^t below any fp32 effect
            long long cut_ll = r_row + (long long)t_d + 8;
            long long cut4   = ((cut_ll + 3) / 4) * 4;     // multiple of 4 rows
            if (cut4 < (long long)i) cut4 = i;
            int cut = (cut4 > (long long)steps) ? steps : (int)cut4;

            s_nrows = i; s_r = r_row; s_cut = cut;
            s_S = S; s_Irec = I; s_A = (float)Ad; s_Rinf = (float)Rinf; s_c = c;
        } else {
            // Fallback: finish serially to gmem with exact R from the chain
            // (redundant identical writes across blocks are benign).
            s_nrows = i; s_r = steps - 1; s_cut = steps;
            for (; i < steps; ++i) {
                float u  = __fmaf_rn(beff, S, omg);
                float v  = __fmul_rn(beff, I);
                float nI = __fmul_rn(I, u);
                float nS = __fmaf_rn(-v, S, S);
                float nR = __fmaf_rn(g, I, R);
                S = nS; I = nI; R = nR;
                out[3*i] = S; out[3*i+1] = I; out[3*i+2] = R;
            }
            s_S = S; s_Irec = I; s_A = 0.0f; s_Rinf = R; s_c = 0.0;
        }
    }

    __syncthreads();

    const int gsize = gridDim.x * NTHREADS;
    const int gtid  = blockIdx.x * NTHREADS + tid;

    const int   nrows = s_nrows;       // multiple of 4 when frozen
    const int   r     = s_r;
    const int   cut   = s_cut;
    const float S     = s_S;
    const float Irec  = s_Irec;
    const float A     = s_A;
    const float Rinf  = s_Rinf;
    const float pop   = s_pop;
    const double c    = s_c;

    // ---- (a) Head rows [0, nrows): gather from s_SI; R = pop - S - I -------
    {
        const int nelem = 3 * nrows;
        for (int e = gtid; e < nelem; e += gsize) {
            const int k    = e / 3;
            const int comp = e - 3 * k;
            const float2 si = s_SI[k];
            float val;
            if (comp == 0)      val = si.x;
            else if (comp == 1) val = si.y;
            else                val = (k == 0) ? s_x2
                                     : __fsub_rn(__fsub_rn(pop, si.x), si.y);
            out[e] = val;
        }
    }

    // ---- (b) Transition rows [nrows, cut): geometric closed form -----------
    {
        const int eBeg = 3 * nrows;
        const int eEnd = 3 * cut;
        for (int e = eBeg + gtid; e < eEnd; e += gsize) {
            const int k    = e / 3;
            const int comp = e - 3 * k;
            const float p  = exp2f((float)((double)(k - r) * c));
            out[e] = (comp == 0) ? S
                   : (comp == 1) ? __fmul_rn(Irec, p)
                                 : __fmaf_rn(-A, p, Rinf);
        }
    }

    // ---- (c) Constant region [cut, steps): (S, 0, Rinf) --------------------
    // 1 float4/thread-iteration grid-stride (at the L2-write cap).
    // 3*cut % 12 == 0 -> start4 valid; phase = j % 3, strength-reduced:
    // gsize % 3 == 1, so the phase rotates +1 per iteration.
    {
        const int n4     = total_elems / 4;
        const int start4 = (3 * cut) / 4;

        const float4 P0 = make_float4(S,    0.0f, Rinf, S);
        const float4 P1 = make_float4(0.0f, Rinf, S,    0.0f);
        const float4 P2 = make_float4(Rinf, S,    0.0f, Rinf);

        float4* out4 = reinterpret_cast<float4*>(out);
        int j  = start4 + gtid;
        int ph = j % 3;
        const int phinc = gsize % 3;                 // 592*256 % 3 == 1
        for (; j < n4; j += gsize) {
            out4[j] = (ph == 0) ? P0 : ((ph == 1) ? P1 : P2);
            ph += phinc; if (ph >= 3) ph -= 3;
        }

        // Scalar remainder (total_elems % 4 != 0 — not hit for steps = 4M).
        if (gtid == 0) {
            for (int e = n4 * 4; e < total_elems; ++e) {
                const int k    = e / 3;
                const int comp = e - 3 * k;
                if (k >= cut)
                    out[e] = (comp == 0) ? S : ((comp == 1) ? 0.0f : Rinf);
                else if (k >= nrows) {
                    const float p = exp2f((float)((double)(k - r) * c));
                    out[e] = (comp == 0) ? S
                           : (comp == 1) ? __fmul_rn(Irec, p)
                                         : __fmaf_rn(-A, p, Rinf);
                } else {
                    const float2 si = s_SI[k];
                    out[e] = (comp == 0) ? si.x
                           : (comp == 1) ? si.y
                                         : __fsub_rn(__fsub_rn(pop, si.x), si.y);
                }
            }
        }
    }
}

extern "C" void kernel_launch(void* const* d_in, const int* in_sizes, int n_in,
                              void* d_out, int out_size)
{
    const float* x  = (const float*)d_in[0];
    const float* bw = (const float*)d_in[1];
    const float* gw = (const float*)d_in[2];
    float* out = (float*)d_out;

    const int steps = out_size / 3;

    sir_fused_kernel<<<NBLOCKS, NTHREADS>>>(x, bw, gw, steps, out_size, out);
}